// round 2
// baseline (speedup 1.0000x reference)
#include <cuda_runtime.h>
#include <cuda_bf16.h>
#include <math_constants.h>

// Problem constants
#define B       16
#define C       64
#define HW      4096          // 64*64 plane
#define K       1024
#define NPIX    65536         // B*HW
#define QSIZE   4194304       // B*C*HW
#define OFF_LOSS 4194304
#define OFF_PERP 4194305
#define OFF_IDX  4194306
#define OFF_ENC  4259842
#define ENC_ELEMS 67108864ULL

#define PIX_PER_BLOCK 128
#define NBLOCKS (NPIX / PIX_PER_BLOCK)   // 512
#define KT 64
#define KT_PAD 68

// Scratch (no device allocation allowed -> __device__ globals)
__device__ float d_wsq[K];
__device__ int   d_counts[K];
__device__ float d_loss_partial[NBLOCKS];

// ---------------------------------------------------------------------------
// Prep: zero histogram, compute ||w_k||^2 (sub-ulp vs grid; order irrelevant)
// ---------------------------------------------------------------------------
__global__ void vq_prep(const float* __restrict__ weight) {
    int t = threadIdx.x;          // 1024 threads
    d_counts[t] = 0;
    const float* w = weight + (size_t)t * C;
    float s = 0.f;
#pragma unroll
    for (int c = 0; c < C; c++) s = __fadd_rn(s, __fmul_rn(w[c], w[c]));
    d_wsq[t] = s;
}

// ---------------------------------------------------------------------------
// Main: per-pixel argmin over K codes, replicating the reference's rounding:
//   d_nk = fl( fl(X_n + W_k) - 2*m_nk ),  X_n = sequential sum of fl(x_c^2)
// One block = 128 consecutive pixels; one thread = 1 pixel.
// ---------------------------------------------------------------------------
__global__ __launch_bounds__(128) void vq_main(const float* __restrict__ in,
                                               const float* __restrict__ weight,
                                               float* __restrict__ out) {
    __shared__ float wt_s[C * KT_PAD];
    __shared__ float red[4];

    const int t     = threadIdx.x;
    const int b     = blockIdx.x >> 5;
    const int chunk = blockIdx.x & 31;
    const int p     = chunk * PIX_PER_BLOCK + t;

    const float* xin = in + (size_t)b * C * HW + p;

    float x[C];
#pragma unroll
    for (int c = 0; c < C; c++) x[c] = xin[(size_t)c * HW];   // coalesced across t

    // X = ||x||^2, sequential, mul-then-add (no fma) to mirror XLA's per-row
    // sequential reduce. This value's exact bits set the rounding residuals.
    float X = 0.f;
#pragma unroll
    for (int c = 0; c < C; c++) X = __fadd_rn(X, __fmul_rn(x[c], x[c]));

    float best = CUDART_INF_F;
    int   bidx = 0;

    for (int k0 = 0; k0 < K; k0 += KT) {
        __syncthreads();
        // weight tile transposed: wt_s[c][kk] = weight[k0+kk][c]
#pragma unroll
        for (int i = 0; i < (KT * C) / PIX_PER_BLOCK; i++) {
            int idx = i * PIX_PER_BLOCK + t;
            int kk = idx >> 6;
            int c  = idx & 63;
            wt_s[c * KT_PAD + kk] = weight[(size_t)(k0 + kk) * C + c];
        }
        __syncthreads();

#pragma unroll 1
        for (int g = 0; g < KT / 4; g++) {
            float ax = 0.f, ay = 0.f, az = 0.f, aw = 0.f;
#pragma unroll
            for (int c = 0; c < C; c++) {
                float4 wv = *reinterpret_cast<const float4*>(&wt_s[c * KT_PAD + g * 4]);
                ax = fmaf(x[c], wv.x, ax);   // dot-order noise is sub-ulp(64): fine
                ay = fmaf(x[c], wv.y, ay);
                az = fmaf(x[c], wv.z, az);
                aw = fmaf(x[c], wv.w, aw);
            }
            const int kb = k0 + g * 4;
            // Reference rounding pipeline: fl(fl(X + W_k) - 2*m)
            float s0 = __fsub_rn(__fadd_rn(X, __ldg(&d_wsq[kb + 0])), __fadd_rn(ax, ax));
            float s1 = __fsub_rn(__fadd_rn(X, __ldg(&d_wsq[kb + 1])), __fadd_rn(ay, ay));
            float s2 = __fsub_rn(__fadd_rn(X, __ldg(&d_wsq[kb + 2])), __fadd_rn(az, az));
            float s3 = __fsub_rn(__fadd_rn(X, __ldg(&d_wsq[kb + 3])), __fadd_rn(aw, aw));
            // ascending k + strict '<' == jnp first-occurrence argmin
            if (s0 < best) { best = s0; bidx = kb + 0; }
            if (s1 < best) { best = s1; bidx = kb + 1; }
            if (s2 < best) { best = s2; bidx = kb + 2; }
            if (s3 < best) { best = s3; bidx = kb + 3; }
        }
    }

    // ---- epilogue ----
    const float* wbest = weight + (size_t)bidx * C;
    float* outq = out + (size_t)b * C * HW + p;
    float lsum = 0.f;
#pragma unroll
    for (int c = 0; c < C; c++) {
        float wv = wbest[c];
        float dd = __fsub_rn(wv, x[c]);                 // fl(w - x)
        outq[(size_t)c * HW] = __fadd_rn(x[c], dd);     // STE: fl(x + fl(w - x))
        lsum = fmaf(dd, dd, lsum);                      // loss uses (w - x)^2
    }

    const int n = b * HW + p;
    out[OFF_IDX + n] = (float)bidx;
    out[OFF_ENC + (size_t)n * K + bidx] = 1.0f;
    atomicAdd(&d_counts[bidx], 1);

#pragma unroll
    for (int o = 16; o > 0; o >>= 1) lsum += __shfl_down_sync(0xFFFFFFFFu, lsum, o);
    if ((t & 31) == 0) red[t >> 5] = lsum;
    __syncthreads();
    if (t == 0) d_loss_partial[blockIdx.x] = (red[0] + red[1]) + (red[2] + red[3]);
}

// ---------------------------------------------------------------------------
// Finalize: perplexity from histogram, commitment loss from block partials
// ---------------------------------------------------------------------------
__global__ void vq_finalize(float* __restrict__ out) {
    __shared__ float sh[K];
    __shared__ float sh2[NBLOCKS];
    int t = threadIdx.x;  // 1024

    float pr = (float)d_counts[t] * (1.0f / (float)NPIX);
    sh[t] = pr * logf(pr + 1e-10f);
    if (t < NBLOCKS) sh2[t] = d_loss_partial[t];
    __syncthreads();

    for (int s = K / 2; s > 0; s >>= 1) {
        if (t < s) sh[t] += sh[t + s];
        if (t < s && s <= NBLOCKS / 2) sh2[t] += sh2[t + s];
        __syncthreads();
    }
    if (t == 0) {
        out[OFF_LOSS] = 0.25f * sh2[0] / (float)QSIZE;
        out[OFF_PERP] = expf(-sh[0]);
    }
}

// ---------------------------------------------------------------------------
extern "C" void kernel_launch(void* const* d_in, const int* in_sizes, int n_in,
                              void* d_out, int out_size) {
    const float* in     = (const float*)d_in[0];
    const float* weight = (const float*)d_in[1];
    float* out = (float*)d_out;

    cudaMemsetAsync(out + OFF_ENC, 0, ENC_ELEMS * sizeof(float));
    vq_prep<<<1, K>>>(weight);
    vq_main<<<NBLOCKS, PIX_PER_BLOCK>>>(in, weight, out);
    vq_finalize<<<1, K>>>(out);
}

// round 3
// speedup vs baseline: 1.3381x; 1.3381x over previous
#include <cuda_runtime.h>
#include <cuda_bf16.h>
#include <math_constants.h>

// Problem constants
#define B       16
#define C       64
#define HW      4096
#define K       1024
#define NPIX    65536
#define QSIZE   4194304
#define OFF_LOSS 4194304
#define OFF_PERP 4194305
#define OFF_IDX  4194306
#define OFF_ENC  4259842          // NOTE: *4 bytes is 8B- but not 16B-aligned -> float2 stores
#define ENC_ELEMS 67108864ULL

#define PIX_PER_BLOCK 64
#define NBLOCKS (NPIX / PIX_PER_BLOCK)   // 1024
#define KT 64
#define KT_PAD 68
#define NTILES (K / KT)                  // 16

// Scratch (no device allocation allowed -> __device__ globals)
__device__ float d_wsq[K];
__device__ int   d_counts[K];
__device__ float d_loss_partial[NBLOCKS];

// ---- packed f32x2 helpers (Blackwell FFMA2; bit-identical per-lane fp32 fma.rn) ----
__device__ __forceinline__ unsigned long long ffma2(unsigned long long a,
                                                    unsigned long long b,
                                                    unsigned long long c) {
    unsigned long long d;
    asm("fma.rn.f32x2 %0, %1, %2, %3;" : "=l"(d) : "l"(a), "l"(b), "l"(c));
    return d;
}
__device__ __forceinline__ unsigned long long pack2(float lo, float hi) {
    unsigned long long d;
    asm("mov.b64 %0, {%1, %2};" : "=l"(d) : "f"(lo), "f"(hi));
    return d;
}
__device__ __forceinline__ void unpack2(unsigned long long v, float& lo, float& hi) {
    asm("mov.b64 {%0, %1}, %2;" : "=f"(lo), "=f"(hi) : "l"(v));
}

// ---------------------------------------------------------------------------
// Prep: zero histogram, compute ||w_k||^2   (8 blocks x 128 threads)
// ---------------------------------------------------------------------------
__global__ void vq_prep(const float* __restrict__ weight) {
    int k = blockIdx.x * 128 + threadIdx.x;    // 0..1023
    d_counts[k] = 0;
    const float* w = weight + (size_t)k * C;
    float s = 0.f;
#pragma unroll
    for (int c = 0; c < C; c++) s = __fadd_rn(s, __fmul_rn(w[c], w[c]));
    d_wsq[k] = s;
}

// ---------------------------------------------------------------------------
// Main: per-pixel argmin over K codes with packed f32x2 FMA.
// Rounding pipeline identical to the passing R2 kernel:
//   d_nk = fl( fl(X_n + W_k) - 2*m_nk ),  X_n sequential mul-then-add.
// One block = 64 pixels; one thread = 1 pixel. Encodings zeroing is
// interleaved with the k-tile loop so DRAM writes hide under FFMA.
// ---------------------------------------------------------------------------
__global__ __launch_bounds__(PIX_PER_BLOCK) void vq_main(const float* __restrict__ in,
                                                         const float* __restrict__ weight,
                                                         float* __restrict__ out) {
    __shared__ float wt_s[C * KT_PAD];
    __shared__ float wsq_s[KT];
    __shared__ float red[2];

    const int t = threadIdx.x;
    const int b     = blockIdx.x >> 6;          // 64 chunks of 64 px per batch plane
    const int chunk = blockIdx.x & 63;
    const int p     = chunk * PIX_PER_BLOCK + t;

    const float* xin = in + (size_t)b * C * HW + p;

    // Load x, compute X = ||x||^2 sequentially (sets the rounding residuals),
    // and keep x duplicated in both lanes of a b64 for FFMA2.
    float X = 0.f;
    unsigned long long x2[C];
#pragma unroll
    for (int c = 0; c < C; c++) {
        float v = xin[(size_t)c * HW];          // coalesced across t
        X = __fadd_rn(X, __fmul_rn(v, v));
        x2[c] = pack2(v, v);
    }

    float best = CUDART_INF_F;
    int   bidx = 0;

    // This block owns encodings rows [blockIdx.x*64, +64) -> 256KB; zero it
    // in 16KB chunks, one per k-tile, spread through the compute.
    float2* encz = (float2*)(out + OFF_ENC + (size_t)blockIdx.x * PIX_PER_BLOCK * K);
    const float2 z2 = make_float2(0.f, 0.f);

    for (int tile = 0; tile < NTILES; tile++) {
        const int k0 = tile * KT;
        __syncthreads();
        // weight tile transposed: wt_s[c][kk] = weight[k0+kk][c]
#pragma unroll
        for (int i = 0; i < (KT * C) / PIX_PER_BLOCK; i++) {   // 64 iters
            int idx = i * PIX_PER_BLOCK + t;
            int kk = idx >> 6;
            int c  = idx & 63;
            wt_s[c * KT_PAD + kk] = weight[(size_t)(k0 + kk) * C + c];
        }
        if (t < KT) wsq_s[t] = d_wsq[k0 + t];
        __syncthreads();

        // zero-chunk: 2048 float2 per tile, 32 per thread (hidden under FFMA)
#pragma unroll
        for (int i = 0; i < 32; i++)
            encz[tile * 2048 + i * PIX_PER_BLOCK + t] = z2;

#pragma unroll 1
        for (int g = 0; g < KT / 4; g++) {
            unsigned long long a01 = 0ULL, a23 = 0ULL;   // packed (0.f,0.f)
#pragma unroll
            for (int c = 0; c < C; c++) {
                // 16B-aligned: row stride 272B, col offset g*16B
                ulonglong2 wv = *reinterpret_cast<const ulonglong2*>(&wt_s[c * KT_PAD + g * 4]);
                a01 = ffma2(x2[c], wv.x, a01);   // lanes: codes kb+0, kb+1
                a23 = ffma2(x2[c], wv.y, a23);   // lanes: codes kb+2, kb+3
            }
            float ax, ay, az, aw;
            unpack2(a01, ax, ay);
            unpack2(a23, az, aw);
            const int kb = k0 + g * 4;
            // Reference rounding pipeline: fl(fl(X + W_k) - 2*m)
            float s0 = __fsub_rn(__fadd_rn(X, wsq_s[g * 4 + 0]), __fadd_rn(ax, ax));
            float s1 = __fsub_rn(__fadd_rn(X, wsq_s[g * 4 + 1]), __fadd_rn(ay, ay));
            float s2 = __fsub_rn(__fadd_rn(X, wsq_s[g * 4 + 2]), __fadd_rn(az, az));
            float s3 = __fsub_rn(__fadd_rn(X, wsq_s[g * 4 + 3]), __fadd_rn(aw, aw));
            // ascending k + strict '<' == jnp first-occurrence argmin
            if (s0 < best) { best = s0; bidx = kb + 0; }
            if (s1 < best) { best = s1; bidx = kb + 1; }
            if (s2 < best) { best = s2; bidx = kb + 2; }
            if (s3 < best) { best = s3; bidx = kb + 3; }
        }
    }

    // all zero-chunks of this block visible before the scatter (block scope)
    __syncthreads();

    // ---- epilogue ----
    const float* wbest = weight + (size_t)bidx * C;
    float* outq = out + (size_t)b * C * HW + p;
    float lsum = 0.f;
#pragma unroll
    for (int c = 0; c < C; c++) {
        float xv, xh;
        unpack2(x2[c], xv, xh);                      // free: lo half of pair
        float wv = wbest[c];                         // weight hot in L2
        float dd = __fsub_rn(wv, xv);                // fl(w - x)
        outq[(size_t)c * HW] = __fadd_rn(xv, dd);    // STE: fl(x + fl(w - x))
        lsum = fmaf(dd, dd, lsum);
    }

    const int n = b * HW + p;
    out[OFF_IDX + n] = (float)bidx;
    out[OFF_ENC + (size_t)n * K + bidx] = 1.0f;      // rows zeroed above by this block
    atomicAdd(&d_counts[bidx], 1);

    // deterministic loss partial (2 warps)
#pragma unroll
    for (int o = 16; o > 0; o >>= 1) lsum += __shfl_down_sync(0xFFFFFFFFu, lsum, o);
    if ((t & 31) == 0) red[t >> 5] = lsum;
    __syncthreads();
    if (t == 0) d_loss_partial[blockIdx.x] = red[0] + red[1];
}

// ---------------------------------------------------------------------------
// Finalize (split in two so launches/call = 4 -> ncu -s5 profiles vq_main)
// ---------------------------------------------------------------------------
__global__ void vq_fin_loss(float* __restrict__ out) {
    __shared__ float sh[NBLOCKS];
    int t = threadIdx.x;                  // 1024
    sh[t] = d_loss_partial[t];
    __syncthreads();
    for (int s = NBLOCKS / 2; s > 0; s >>= 1) {
        if (t < s) sh[t] += sh[t + s];
        __syncthreads();
    }
    if (t == 0) out[OFF_LOSS] = 0.25f * sh[0] / (float)QSIZE;
}

__global__ void vq_fin_perp(float* __restrict__ out) {
    __shared__ float sh[K];
    int t = threadIdx.x;                  // 1024
    float pr = (float)d_counts[t] * (1.0f / (float)NPIX);
    sh[t] = pr * logf(pr + 1e-10f);
    __syncthreads();
    for (int s = K / 2; s > 0; s >>= 1) {
        if (t < s) sh[t] += sh[t + s];
        __syncthreads();
    }
    if (t == 0) out[OFF_PERP] = expf(-sh[0]);
}

// ---------------------------------------------------------------------------
extern "C" void kernel_launch(void* const* d_in, const int* in_sizes, int n_in,
                              void* d_out, int out_size) {
    const float* in     = (const float*)d_in[0];
    const float* weight = (const float*)d_in[1];
    float* out = (float*)d_out;

    vq_prep<<<8, 128>>>(weight);
    vq_main<<<NBLOCKS, PIX_PER_BLOCK>>>(in, weight, out);
    vq_fin_loss<<<1, NBLOCKS>>>(out);
    vq_fin_perp<<<1, K>>>(out);
}